// round 14
// baseline (speedup 1.0000x reference)
#include <cuda_runtime.h>
#include <cuda_bf16.h>
#include <cstdint>

// Problem constants
#define CIN   1024
#define Tlen  4096
#define DVQ   1024
#define KCB   2048
#define TOK   16384      // B * T/2

// ---------------------------------------------------------------------------
// Scratch (static device arrays)
__device__ float               g_H[TOK * DVQ];          // fp32 H, bit-equal chain to R1
__device__ __nv_bfloat16       g_Hb[TOK * DVQ];         // bf16 H
__device__ __nv_bfloat16       g_Sb[(size_t)TOK * KCB]; // approx scores bf16, [m][k]
__device__ unsigned int        g_maxOrd[TOK];
__device__ int                 g_cand[TOK * 32];
__device__ int                 g_candcnt[TOK];
__device__ int                 g_idx[TOK];
__device__ float               g_cn[KCB];               // 0.5 * |c_k|^2
__device__ float               g_hnp[8 * TOK];          // per-nblock partial |H_m|^2
__device__ float               g_sbest[TOK];            // winning exact score
__device__ float               g_P[KCB * CIN];          // P[k][o] = Wout·cb_k + b_out
__device__ __nv_bfloat16       g_CBh[KCB * DVQ];
__device__ __nv_bfloat16       g_CBl[KCB * DVQ];
__device__ __nv_bfloat16       g_WOh[CIN * DVQ];
__device__ __nv_bfloat16       g_WOl[CIN * DVQ];

// ---------------------------------------------------------------------------
// Baseline-PTX helpers
__device__ __forceinline__ uint32_t smem_u32(const void* p) {
    uint32_t a;
    asm("{ .reg .u64 t; cvta.to.shared.u64 t, %1; cvt.u32.u64 %0, t; }" : "=r"(a) : "l"(p));
    return a;
}
__device__ __forceinline__ void ldsm4(uint32_t* r, uint32_t addr) {
    asm volatile("ldmatrix.sync.aligned.m8n8.x4.shared.b16 {%0,%1,%2,%3}, [%4];"
                 : "=r"(r[0]), "=r"(r[1]), "=r"(r[2]), "=r"(r[3]) : "r"(addr));
}
__device__ __forceinline__ void ldsm2(uint32_t* r, uint32_t addr) {
    asm volatile("ldmatrix.sync.aligned.m8n8.x2.shared.b16 {%0,%1}, [%2];"
                 : "=r"(r[0]), "=r"(r[1]) : "r"(addr));
}
__device__ __forceinline__ void mma16816(float* c, const uint32_t* a, const uint32_t* b) {
    asm volatile(
        "mma.sync.aligned.m16n8k16.row.col.f32.bf16.bf16.f32 "
        "{%0,%1,%2,%3}, {%4,%5,%6,%7}, {%8,%9}, {%0,%1,%2,%3};\n"
        : "+f"(c[0]), "+f"(c[1]), "+f"(c[2]), "+f"(c[3])
        : "r"(a[0]), "r"(a[1]), "r"(a[2]), "r"(a[3]), "r"(b[0]), "r"(b[1]));
}
__device__ __forceinline__ void cpasync16(uint32_t dst, const void* src) {
    asm volatile("cp.async.cg.shared.global [%0], [%1], 16;" :: "r"(dst), "l"(src));
}
#define CP_COMMIT() asm volatile("cp.async.commit_group;" ::: "memory")
#define CP_WAIT0()  asm volatile("cp.async.wait_group 0;" ::: "memory")

__device__ __forceinline__ uint32_t swz(int row, int bcol) {
    return (uint32_t)(row * 128 + ((((bcol >> 4) ^ (row & 7)) << 4) | (bcol & 15)));
}
__device__ __forceinline__ uint32_t pack2(__nv_bfloat16 a, __nv_bfloat16 b) {
    __nv_bfloat162 t; t.x = a; t.y = b;
    return *reinterpret_cast<uint32_t*>(&t);
}

// Warp-tile mma over one 128x128x32 chunk.
__device__ __forceinline__ void mma_chunk(uint32_t sA, uint32_t sB, int wm, int wn,
                                          int lane, float acc[4][4][4]) {
#pragma unroll
    for (int ks = 0; ks < 2; ks++) {
        uint32_t a[4][4], b[4][2];
#pragma unroll
        for (int mi = 0; mi < 4; mi++) {
            int row = wm + 16 * mi + (lane & 15);
            int bcol = ks * 32 + ((lane >> 4) << 4);
            ldsm4(a[mi], sA + swz(row, bcol));
        }
#pragma unroll
        for (int ni = 0; ni < 4; ni++) {
            int row = wn + 8 * ni + (lane & 7);
            int bcol = ks * 32 + (((lane >> 3) & 1) << 4);
            ldsm2(b[ni], sB + swz(row, bcol));
        }
#pragma unroll
        for (int mi = 0; mi < 4; mi++)
#pragma unroll
            for (int ni = 0; ni < 4; ni++)
                mma16816(acc[mi][ni], a[mi], b[ni]);
    }
}

// ---------------------------------------------------------------------------
// Device body: GEMM1 (fp32 FFMA, chain bit-identical to R1/R7/R8/R13)
__device__ __forceinline__ void dev_gemm1(char* smem, const float* __restrict__ x,
                                          const float* __restrict__ w_in,
                                          const float* __restrict__ b_in,
                                          int mblk, int nblk) {
    const uint32_t sb = smem_u32(smem);
    const int tid = threadIdx.x;
    const int ty = tid >> 4, tx = tid & 15;
    const int m0 = mblk * 128;
    const int n0 = nblk * 128;
    const int bb = m0 >> 11;
    const int tt0 = m0 & 2047;

    const int ac0 = tid,        akc0 = ac0 >> 6, apos0 = ac0 & 63;
    const int ac1 = tid + 256,  akc1 = ac1 >> 6, apos1 = ac1 & 63;
    const int brow = tid >> 1, bhalf = tid & 1;

    float acc[8][8];
#pragma unroll
    for (int i = 0; i < 8; i++)
#pragma unroll
        for (int j = 0; j < 8; j++) acc[i][j] = 0.f;

    float4 bp0, bp1;
    {
        const float* xbase = x + (size_t)((bb << 10)) * Tlen + (tt0 << 1);
        cpasync16(sb + (uint32_t)(akc0 * 1024 + apos0 * 16),
                  xbase + (size_t)akc0 * Tlen + apos0 * 4);
        cpasync16(sb + (uint32_t)(akc1 * 1024 + apos1 * 16),
                  xbase + (size_t)akc1 * Tlen + apos1 * 4);
        CP_COMMIT();
        const float* wp = w_in + (size_t)(n0 + brow) * 2048 + bhalf * 8;
        bp0 = *(const float4*)(wp);
        bp1 = *(const float4*)(wp + 4);
        const float* b4 = (const float*)&bp0;
        #pragma unroll
        for (int w = 0; w < 4; w++)
            *(float*)(smem + 8192 + (bhalf * 8 + w) * 512 + brow * 4) = b4[w];
        const float* b5 = (const float*)&bp1;
        #pragma unroll
        for (int w = 0; w < 4; w++)
            *(float*)(smem + 8192 + (bhalf * 8 + 4 + w) * 512 + brow * 4) = b5[w];
    }

#pragma unroll 1
    for (int c = 0; c < 128; c++) {
        const uint32_t bufo = (uint32_t)(c & 1) * 16384u;
        CP_WAIT0();
        __syncthreads();

        if (c < 127) {
            const int k1 = (c + 1) * 16;
            const uint32_t nb = (uint32_t)((c + 1) & 1) * 16384u;
            const float* xbase = x + (size_t)((bb << 10) + (k1 >> 1)) * Tlen + (tt0 << 1);
            cpasync16(sb + nb + (uint32_t)(akc0 * 1024 + apos0 * 16),
                      xbase + (size_t)akc0 * Tlen + apos0 * 4);
            cpasync16(sb + nb + (uint32_t)(akc1 * 1024 + apos1 * 16),
                      xbase + (size_t)akc1 * Tlen + apos1 * 4);
            CP_COMMIT();
            const float* wp = w_in + (size_t)(n0 + brow) * 2048 + k1 + bhalf * 8;
            bp0 = *(const float4*)(wp);
            bp1 = *(const float4*)(wp + 4);
        }

        const char* Ab = smem + bufo;
        const char* Bb = smem + bufo + 8192;
#pragma unroll
        for (int kc = 0; kc < 8; kc++) {
            float4 av[4];
#pragma unroll
            for (int q = 0; q < 4; q++)
                av[q] = *(const float4*)(Ab + kc * 1024 + ty * 64 + q * 16);
            const float* af = (const float*)av;
#pragma unroll
            for (int p = 0; p < 2; p++) {
                float4 bv0 = *(const float4*)(Bb + (2 * kc + p) * 512 + tx * 32);
                float4 bv1 = *(const float4*)(Bb + (2 * kc + p) * 512 + tx * 32 + 16);
                const float bf8[8] = {bv0.x, bv0.y, bv0.z, bv0.w,
                                      bv1.x, bv1.y, bv1.z, bv1.w};
#pragma unroll
                for (int i = 0; i < 8; i++)
#pragma unroll
                    for (int j = 0; j < 8; j++)
                        acc[i][j] = fmaf(af[2 * i + p], bf8[j], acc[i][j]);
            }
        }

        if (c < 127) {
            const uint32_t nb = (uint32_t)((c + 1) & 1) * 16384u;
            const float* b4 = (const float*)&bp0;
            #pragma unroll
            for (int w = 0; w < 4; w++)
                *(float*)(smem + nb + 8192 + (bhalf * 8 + w) * 512 + brow * 4) = b4[w];
            const float* b5 = (const float*)&bp1;
            #pragma unroll
            for (int w = 0; w < 4; w++)
                *(float*)(smem + nb + 8192 + (bhalf * 8 + 4 + w) * 512 + brow * 4) = b5[w];
        }
    }

    __syncthreads();
    float* sq = (float*)smem;              // [128 rows][17]
#pragma unroll
    for (int i = 0; i < 8; i++) {
        int m = m0 + ty * 8 + i;
        float* hp = g_H + (size_t)m * DVQ + n0 + tx * 8;
        float vv[8];
#pragma unroll
        for (int j = 0; j < 8; j++) vv[j] = acc[i][j] + b_in[n0 + tx * 8 + j];
        *(float4*)(hp)     = make_float4(vv[0], vv[1], vv[2], vv[3]);
        *(float4*)(hp + 4) = make_float4(vv[4], vv[5], vv[6], vv[7]);
        __nv_bfloat16 hb[8];
#pragma unroll
        for (int j = 0; j < 8; j++) hb[j] = __float2bfloat16(vv[j]);
        *(uint4*)(g_Hb + (size_t)m * DVQ + n0 + tx * 8) = *(uint4*)hb;
        float part = 0.f;
#pragma unroll
        for (int j = 0; j < 8; j++) part += vv[j] * vv[j];
        sq[(ty * 8 + i) * 17 + tx] = part;
    }
    __syncthreads();
    if (tid < 128) {
        float s = 0.f;
        #pragma unroll
        for (int t = 0; t < 16; t++) s += sq[tid * 17 + t];
        g_hnp[nblk * TOK + m0 + tid] = s;
    }
}

// ---------------------------------------------------------------------------
// Device body: GEMM2 (bf16 HMMA scores -> g_Sb[m][k] + row max)
#define SC_STRIDE 132
__device__ __forceinline__ void dev_gemm2(char* smem, int mblk, int nblk) {
    const uint32_t sb = smem_u32(smem);
    const int tid = threadIdx.x, lane = tid & 31, wid = tid >> 5;
    const int wm = (wid & 1) * 64, wn = (wid >> 1) * 32;
    const int m0 = mblk * 128, n0 = nblk * 128;

    float acc[4][4][4];
#pragma unroll
    for (int i = 0; i < 4; i++)
#pragma unroll
        for (int j = 0; j < 4; j++)
#pragma unroll
            for (int q = 0; q < 4; q++) acc[i][j][q] = 0.f;

    const int lrow = tid >> 2, luc = tid & 3;
    const char* srcA = (const char*)(g_Hb  + (size_t)(m0 + lrow) * DVQ) + luc * 16;
    const char* srcA2 = (const char*)(g_Hb + (size_t)(m0 + 64 + lrow) * DVQ) + luc * 16;
    const char* srcB = (const char*)(g_CBh + (size_t)(n0 + lrow) * DVQ) + luc * 16;
    const char* srcB2 = (const char*)(g_CBh + (size_t)(n0 + 64 + lrow) * DVQ) + luc * 16;
    const uint32_t off1 = (uint32_t)(lrow * 128 + ((luc ^ (lrow & 7)) << 4));
    const uint32_t off2 = (uint32_t)((lrow + 64) * 128 + ((luc ^ (lrow & 7)) << 4));

    {
        cpasync16(sb + off1, srcA);
        cpasync16(sb + off2, srcA2);
        cpasync16(sb + 32768u + off1, srcB);
        cpasync16(sb + 32768u + off2, srcB2);
        CP_COMMIT();
    }
#pragma unroll 1
    for (int c = 0; c < 32; c++) {
        CP_WAIT0();
        __syncthreads();
        if (c < 31) {
            const uint32_t ao = (uint32_t)((c + 1) & 1) * 16384u;
            const uint32_t bo = 32768u + (uint32_t)((c + 1) & 1) * 16384u;
            const int kby = (c + 1) * 64;
            cpasync16(sb + ao + off1, srcA + kby);
            cpasync16(sb + ao + off2, srcA2 + kby);
            cpasync16(sb + bo + off1, srcB + kby);
            cpasync16(sb + bo + off2, srcB2 + kby);
            CP_COMMIT();
        }
        mma_chunk(sb + (uint32_t)(c & 1) * 16384u, sb + 32768u + (uint32_t)(c & 1) * 16384u,
                  wm, wn, lane, acc);
    }
    __syncthreads();

    float* sc = (float*)smem;
    const int g = lane >> 2, lam = lane & 3;
#pragma unroll
    for (int mi = 0; mi < 4; mi++)
#pragma unroll
        for (int ni = 0; ni < 4; ni++) {
            const int col = wn + 8 * ni + 2 * lam;
            const float cn0 = __ldg(g_cn + n0 + col), cn1 = __ldg(g_cn + n0 + col + 1);
#pragma unroll
            for (int h = 0; h < 2; h++) {
                const int row = wm + 16 * mi + g + 8 * h;
                sc[row * SC_STRIDE + col]     = acc[mi][ni][2 * h + 0] - cn0;
                sc[row * SC_STRIDE + col + 1] = acc[mi][ni][2 * h + 1] - cn1;
            }
        }
    __syncthreads();

    {
        const int cp = (tid & 63) * 2;
        const int rg = tid >> 6;
        #pragma unroll 4
        for (int r = rg * 32; r < rg * 32 + 32; r++) {
            uint32_t v = pack2(__float2bfloat16(sc[r * SC_STRIDE + cp]),
                               __float2bfloat16(sc[r * SC_STRIDE + cp + 1]));
            *(uint32_t*)(g_Sb + (size_t)(m0 + r) * KCB + n0 + cp) = v;
        }
    }
    {
        const int row = tid & 127, half = tid >> 7;
        float mx = -3.4e38f;
        #pragma unroll 4
        for (int j = 0; j < 64; j++) mx = fmaxf(mx, sc[row * SC_STRIDE + half * 64 + j]);
        float* pmax = (float*)(smem + 67584);
        pmax[row * 2 + half] = mx;
        __syncthreads();
        if (tid < 128) {
            float m2 = fmaxf(pmax[tid * 2], pmax[tid * 2 + 1]);
            unsigned u = __float_as_uint(m2);
            u = (m2 < 0.f) ? ~u : (u | 0x80000000u);
            atomicMax(&g_maxOrd[m0 + tid], u);
        }
    }
}

// ---------------------------------------------------------------------------
// Device body: P-GEMM (bf16 HMMA 3-product): P[k][o] = Wout·cb_k + b_out
__device__ __forceinline__ void dev_pgemm(char* smem, const float* __restrict__ b_out,
                                          int mblk, int nblk) {
    const uint32_t sb = smem_u32(smem);
    const int tid = threadIdx.x, lane = tid & 31, wid = tid >> 5;
    const int wm = (wid & 1) * 64, wn = (wid >> 1) * 32;
    const int m0 = mblk * 128, n0 = nblk * 128;

    float acc[4][4][4];
#pragma unroll
    for (int i = 0; i < 4; i++)
#pragma unroll
        for (int j = 0; j < 4; j++)
#pragma unroll
            for (int q = 0; q < 4; q++) acc[i][j][q] = 0.f;

    const int lrow = tid >> 2, luc = tid & 3;
    const uint32_t off1 = (uint32_t)(lrow * 128 + ((luc ^ (lrow & 7)) << 4));
    const uint32_t off2 = (uint32_t)((lrow + 64) * 128 + ((luc ^ (lrow & 7)) << 4));
    const size_t rowA1 = (size_t)(m0 + lrow) * DVQ;
    const size_t rowA2 = (size_t)(m0 + 64 + lrow) * DVQ;
    const size_t rowB1 = (size_t)(n0 + lrow) * DVQ;
    const size_t rowB2 = (size_t)(n0 + 64 + lrow) * DVQ;

    {
        cpasync16(sb + off1, (const char*)(g_CBh + rowA1) + luc * 16);
        cpasync16(sb + off2, (const char*)(g_CBh + rowA2) + luc * 16);
        cpasync16(sb + 32768u + off1, (const char*)(g_WOh + rowB1) + luc * 16);
        cpasync16(sb + 32768u + off2, (const char*)(g_WOh + rowB2) + luc * 16);
        CP_COMMIT();
    }
#pragma unroll 1
    for (int c = 0; c < 96; c++) {
        CP_WAIT0();
        __syncthreads();
        if (c < 95) {
            const int c1 = c + 1;
            const int seg = c1 >> 5;
            const int kby = (c1 & 31) * 64 + luc * 16;
            const __nv_bfloat16* Ab = (seg == 2) ? g_CBl : g_CBh;
            const __nv_bfloat16* Bb = (seg == 1) ? g_WOl : g_WOh;
            const uint32_t ao = (uint32_t)(c1 & 1) * 16384u;
            const uint32_t bo = 32768u + (uint32_t)(c1 & 1) * 16384u;
            cpasync16(sb + ao + off1, (const char*)(Ab + rowA1) + kby);
            cpasync16(sb + ao + off2, (const char*)(Ab + rowA2) + kby);
            cpasync16(sb + bo + off1, (const char*)(Bb + rowB1) + kby);
            cpasync16(sb + bo + off2, (const char*)(Bb + rowB2) + kby);
            CP_COMMIT();
        }
        mma_chunk(sb + (uint32_t)(c & 1) * 16384u, sb + 32768u + (uint32_t)(c & 1) * 16384u,
                  wm, wn, lane, acc);
    }

    const int g = lane >> 2, lam = lane & 3;
#pragma unroll
    for (int mi = 0; mi < 4; mi++)
#pragma unroll
        for (int ni = 0; ni < 4; ni++) {
            const int col = n0 + wn + 8 * ni + 2 * lam;
            const float b0 = __ldg(b_out + col), b1 = __ldg(b_out + col + 1);
#pragma unroll
            for (int h = 0; h < 2; h++) {
                const int k = m0 + wm + 16 * mi + g + 8 * h;
                *(float2*)(g_P + (size_t)k * CIN + col) =
                    make_float2(acc[mi][ni][2 * h + 0] + b0,
                                acc[mi][ni][2 * h + 1] + b1);
            }
        }
}

// ---------------------------------------------------------------------------
// L1: fused preps. blocks: [0,2048) cnorm | [2048,10240) prep_cb |
// [10240,14336) prep_wout | [14336,14400) init
__global__ __launch_bounds__(256) void k_prep_fused(const float* __restrict__ cb,
                                                    const float* __restrict__ w_out) {
    const int b = blockIdx.x;
    if (b < 2048) {
        // cnorm: arithmetic byte-identical to original k_cnorm
        __shared__ float red[256];
        const int k = b;
        const float* row = cb + k * DVQ;
        float s = 0.f;
        for (int d = threadIdx.x; d < DVQ; d += 256) { float v = row[d]; s += v * v; }
        red[threadIdx.x] = s;
        __syncthreads();
        for (int off = 128; off > 0; off >>= 1) {
            if (threadIdx.x < off) red[threadIdx.x] += red[threadIdx.x + off];
            __syncthreads();
        }
        if (threadIdx.x == 0) g_cn[k] = 0.5f * red[0];
    } else if (b < 10240) {
        int i = (b - 2048) * 256 + threadIdx.x;
        float v = cb[i];
        __nv_bfloat16 h = __float2bfloat16(v);
        g_CBh[i] = h;
        g_CBl[i] = __float2bfloat16(v - __bfloat162float(h));
    } else if (b < 14336) {
        int i = (b - 10240) * 256 + threadIdx.x;
        float v = w_out[i];
        __nv_bfloat16 h = __float2bfloat16(v);
        g_WOh[i] = h;
        g_WOl[i] = __float2bfloat16(v - __bfloat162float(h));
    } else {
        int m = (b - 14336) * 256 + threadIdx.x;
        if (m < TOK) g_maxOrd[m] = 0u;
    }
}

// ---------------------------------------------------------------------------
// L2: gemm1 first half (512 blocks) + pgemm (128 blocks)
#define GBIG_SMEM 69632
__global__ __launch_bounds__(256, 2) void k_g1_pg(const float* __restrict__ x,
                                                  const float* __restrict__ w_in,
                                                  const float* __restrict__ b_in,
                                                  const float* __restrict__ b_out) {
    extern __shared__ char smem[];
    const int b = blockIdx.x;
    if (b < 512) {
        dev_gemm1(smem, x, w_in, b_in, b >> 3, b & 7);
    } else {
        const int p = b - 512;
        dev_pgemm(smem, b_out, p >> 3, p & 7);
    }
}

// L3: gemm1 second half (512) + gemm2 first-half tokens (1024)
__global__ __launch_bounds__(256, 2) void k_g1_g2(const float* __restrict__ x,
                                                  const float* __restrict__ w_in,
                                                  const float* __restrict__ b_in) {
    extern __shared__ char smem[];
    const int b = blockIdx.x;
    if (b < 512) {
        dev_gemm1(smem, x, w_in, b_in, 64 + (b >> 3), b & 7);
    } else {
        const int q = b - 512;
        dev_gemm2(smem, q >> 4, q & 15);
    }
}

// L4: gemm2 second-half tokens
__global__ __launch_bounds__(256, 2) void k_gemm2b() {
    extern __shared__ char smem[];
    dev_gemm2(smem, 64 + blockIdx.x, blockIdx.y);
}

// ---------------------------------------------------------------------------
// Collect: one warp per token; vectorized coalesced reads of g_Sb[m][k]
#define DELTA 4.5f
__global__ __launch_bounds__(256) void k_collect() {
    const int lane = threadIdx.x & 31;
    const int m = blockIdx.x * 8 + (threadIdx.x >> 5);
    unsigned u = g_maxOrd[m];
    float mx = (u & 0x80000000u) ? __uint_as_float(u ^ 0x80000000u) : __uint_as_float(~u);
    const float thr = mx - DELTA;
    int cnt = 0;
    const __nv_bfloat16* row = g_Sb + (size_t)m * KCB;
#pragma unroll 1
    for (int j = 0; j < 8; j++) {
        const int k0 = j * 256 + lane * 8;
        uint4 v = *(const uint4*)(row + k0);
        const __nv_bfloat16* e = (const __nv_bfloat16*)&v;
#pragma unroll
        for (int q = 0; q < 8; q++) {
            bool pred = (__bfloat162float(e[q]) >= thr);
            unsigned bal = __ballot_sync(0xFFFFFFFFu, pred);
            if (pred) {
                int pos = cnt + __popc(bal & ((1u << lane) - 1));
                if (pos < 32) g_cand[m * 32 + pos] = k0 + q;
            }
            cnt += __popc(bal);
        }
    }
    if (lane == 0) g_candcnt[m] = cnt < 32 ? cnt : 32;
}

// Exact fp32 rescore: strict sequential ascending-d fmaf chain per candidate.
__global__ __launch_bounds__(128) void k_rescore(const float* __restrict__ cb,
                                                 float* __restrict__ idx_out) {
    const int wid = threadIdx.x >> 5, lid = threadIdx.x & 31;
    const int m = blockIdx.x * 4 + wid;
    const int cnt = g_candcnt[m];
    const float* hp = g_H + (size_t)m * DVQ;

    unsigned long long key = 0ULL;
    if (lid < cnt) {
        const int k = g_cand[m * 32 + lid];
        const float* cp = cb + (size_t)k * DVQ;
        float s = 0.f;
        #pragma unroll 8
        for (int d = 0; d < DVQ; d++) s = fmaf(hp[d], cp[d], s);
        const float scv = s - g_cn[k];
        unsigned uu = __float_as_uint(scv);
        uu = (scv < 0.f) ? ~uu : (uu | 0x80000000u);
        key = ((unsigned long long)uu << 32) |
              (unsigned long long)(0xFFFFFFFFu - (unsigned)k);
    }
#pragma unroll
    for (int o = 16; o > 0; o >>= 1) {
        unsigned long long other = __shfl_xor_sync(0xFFFFFFFFu, key, o);
        if (other > key) key = other;
    }
    if (lid == 0) {
        int bk = (int)(0xFFFFFFFFu - (unsigned)(key & 0xFFFFFFFFu));
        g_idx[m] = bk;
        idx_out[m] = (float)bk;
        unsigned uu = (unsigned)(key >> 32);
        g_sbest[m] = (uu & 0x80000000u) ? __uint_as_float(uu ^ 0x80000000u)
                                        : __uint_as_float(~uu);
    }
}

// ---------------------------------------------------------------------------
// Loss via identity (deterministic)
__global__ void k_loss_final(float* __restrict__ loss_out) {
    __shared__ float red[256];
    const int t = threadIdx.x;
    float acc = 0.f;
    for (int m = t; m < TOK; m += 256) {
        float hn = 0.f;
        #pragma unroll
        for (int b = 0; b < 8; b++) hn += g_hnp[b * TOK + m];
        acc += hn - 2.f * g_sbest[m];
    }
    red[t] = acc;
    __syncthreads();
    for (int off = 128; off > 0; off >>= 1) {
        if (t < off) red[t] += red[t + off];
        __syncthreads();
    }
    if (t == 0)
        loss_out[0] = red[0] / ((float)TOK * (float)DVQ);
}

// ---------------------------------------------------------------------------
// Scatter: out[b,o,2t+{0,1}] = P[idx[m]][o] * mask
__global__ __launch_bounds__(256) void k_scatter(const float* __restrict__ xmask,
                                                 float* __restrict__ out) {
    __shared__ int sidx[128];
    const int tid = threadIdx.x;
    const int m0 = blockIdx.x * 128, n0 = blockIdx.y * 128;
    if (tid < 128) sidx[tid] = g_idx[m0 + tid];
    __syncthreads();

    const int col = tid & 127, half = tid >> 7;
    const int o = n0 + col;
    const int b = m0 >> 11;
    #pragma unroll 4
    for (int r = 0; r < 64; r++) {
        const int rr = half * 64 + r;
        const int m = m0 + rr;
        const int t2 = m & 2047;
        float v = __ldg(g_P + (size_t)sidx[rr] * CIN + o);
        float mk0 = __ldg(xmask + b * Tlen + 2 * t2);
        float mk1 = __ldg(xmask + b * Tlen + 2 * t2 + 1);
        *(float2*)(out + ((size_t)(b * CIN + o)) * Tlen + 2 * t2) =
            make_float2(v * mk0, v * mk1);
    }
}

// ---------------------------------------------------------------------------
extern "C" void kernel_launch(void* const* d_in, const int* in_sizes, int n_in,
                              void* d_out, int out_size) {
    const float* x     = (const float*)d_in[0];
    const float* xmask = (const float*)d_in[1];
    const float* w_in  = (const float*)d_in[2];
    const float* b_in  = (const float*)d_in[3];
    const float* cb    = (const float*)d_in[4];
    const float* w_out = (const float*)d_in[5];
    const float* b_out = (const float*)d_in[6];
    float* out = (float*)d_out;

    const int loss_off = out_size - 1;
    const int idx_off  = out_size - 1 - TOK;

    cudaFuncSetAttribute(k_g1_pg,  cudaFuncAttributeMaxDynamicSharedMemorySize, GBIG_SMEM);
    cudaFuncSetAttribute(k_g1_g2,  cudaFuncAttributeMaxDynamicSharedMemorySize, GBIG_SMEM);
    cudaFuncSetAttribute(k_gemm2b, cudaFuncAttributeMaxDynamicSharedMemorySize, GBIG_SMEM);

    k_prep_fused<<<14400, 256>>>(cb, w_out);
    k_g1_pg<<<640, 256, GBIG_SMEM>>>(x, w_in, b_in, b_out);
    k_g1_g2<<<1536, 256, GBIG_SMEM>>>(x, w_in, b_in);
    k_gemm2b<<<dim3(64, 16), 256, GBIG_SMEM>>>();
    k_collect<<<TOK / 8, 256>>>();
    k_rescore<<<TOK / 4, 128>>>(cb, out + idx_off);
    k_loss_final<<<1, 256>>>(out + loss_off);
    k_scatter<<<dim3(TOK / 128, CIN / 128), 256>>>(xmask, out);
}

// round 15
// speedup vs baseline: 1.0828x; 1.0828x over previous
#include <cuda_runtime.h>
#include <cuda_bf16.h>
#include <cstdint>

// Problem constants
#define CIN   1024
#define Tlen  4096
#define DVQ   1024
#define KCB   2048
#define TOK   16384      // B * T/2

// ---------------------------------------------------------------------------
// Scratch (static device arrays)
__device__ float               g_H[TOK * DVQ];          // fp32 H, bit-equal chain to R1
__device__ __nv_bfloat16       g_Hb[TOK * DVQ];         // bf16 H
__device__ __nv_bfloat16       g_Sb[(size_t)TOK * KCB]; // approx scores bf16, [m][k]
__device__ unsigned int        g_maxOrd[TOK];
__device__ int                 g_cand[TOK * 32];
__device__ int                 g_candcnt[TOK];
__device__ int                 g_idx[TOK];
__device__ float               g_cn[KCB];               // 0.5 * |c_k|^2
__device__ float               g_hnp[8 * TOK];          // per-nblock partial |H_m|^2
__device__ float               g_sbest[TOK];            // winning exact score
__device__ float               g_P[KCB * CIN];          // P[k][o] = Wout·cb_k + b_out
__device__ __nv_bfloat16       g_CBh[KCB * DVQ];
__device__ __nv_bfloat16       g_CBl[KCB * DVQ];
__device__ __nv_bfloat16       g_WOh[CIN * DVQ];
__device__ __nv_bfloat16       g_WOl[CIN * DVQ];

// ---------------------------------------------------------------------------
// Baseline-PTX helpers
__device__ __forceinline__ uint32_t smem_u32(const void* p) {
    uint32_t a;
    asm("{ .reg .u64 t; cvta.to.shared.u64 t, %1; cvt.u32.u64 %0, t; }" : "=r"(a) : "l"(p));
    return a;
}
__device__ __forceinline__ void ldsm4(uint32_t* r, uint32_t addr) {
    asm volatile("ldmatrix.sync.aligned.m8n8.x4.shared.b16 {%0,%1,%2,%3}, [%4];"
                 : "=r"(r[0]), "=r"(r[1]), "=r"(r[2]), "=r"(r[3]) : "r"(addr));
}
__device__ __forceinline__ void ldsm2(uint32_t* r, uint32_t addr) {
    asm volatile("ldmatrix.sync.aligned.m8n8.x2.shared.b16 {%0,%1}, [%2];"
                 : "=r"(r[0]), "=r"(r[1]) : "r"(addr));
}
__device__ __forceinline__ void mma16816(float* c, const uint32_t* a, const uint32_t* b) {
    asm volatile(
        "mma.sync.aligned.m16n8k16.row.col.f32.bf16.bf16.f32 "
        "{%0,%1,%2,%3}, {%4,%5,%6,%7}, {%8,%9}, {%0,%1,%2,%3};\n"
        : "+f"(c[0]), "+f"(c[1]), "+f"(c[2]), "+f"(c[3])
        : "r"(a[0]), "r"(a[1]), "r"(a[2]), "r"(a[3]), "r"(b[0]), "r"(b[1]));
}
__device__ __forceinline__ void cpasync16(uint32_t dst, const void* src) {
    asm volatile("cp.async.cg.shared.global [%0], [%1], 16;" :: "r"(dst), "l"(src));
}
#define CP_COMMIT() asm volatile("cp.async.commit_group;" ::: "memory")
#define CP_WAIT0()  asm volatile("cp.async.wait_group 0;" ::: "memory")

__device__ __forceinline__ uint32_t swz(int row, int bcol) {
    return (uint32_t)(row * 128 + ((((bcol >> 4) ^ (row & 7)) << 4) | (bcol & 15)));
}
__device__ __forceinline__ uint32_t pack2(__nv_bfloat16 a, __nv_bfloat16 b) {
    __nv_bfloat162 t; t.x = a; t.y = b;
    return *reinterpret_cast<uint32_t*>(&t);
}

// Warp-tile mma over one 128x128x32 chunk. acc[4][4][4], warp tile 64x32.
__device__ __forceinline__ void mma_chunk(uint32_t sA, uint32_t sB, int wm, int wn,
                                          int lane, float acc[4][4][4]) {
#pragma unroll
    for (int ks = 0; ks < 2; ks++) {
        uint32_t a[4][4], b[4][2];
#pragma unroll
        for (int mi = 0; mi < 4; mi++) {
            int row = wm + 16 * mi + (lane & 15);
            int bcol = ks * 32 + ((lane >> 4) << 4);
            ldsm4(a[mi], sA + swz(row, bcol));
        }
#pragma unroll
        for (int ni = 0; ni < 4; ni++) {
            int row = wn + 8 * ni + (lane & 7);
            int bcol = ks * 32 + (((lane >> 3) & 1) << 4);
            ldsm2(b[ni], sB + swz(row, bcol));
        }
#pragma unroll
        for (int mi = 0; mi < 4; mi++)
#pragma unroll
            for (int ni = 0; ni < 4; ni++)
                mma16816(acc[mi][ni], a[mi], b[ni]);
    }
}

// ---------------------------------------------------------------------------
// Small prep kernels
__global__ void k_cnorm(const float* __restrict__ cb) {
    __shared__ float red[256];
    int k = blockIdx.x;
    const float* row = cb + k * DVQ;
    float s = 0.f;
    for (int d = threadIdx.x; d < DVQ; d += 256) { float v = row[d]; s += v * v; }
    red[threadIdx.x] = s;
    __syncthreads();
    for (int off = 128; off > 0; off >>= 1) {
        if (threadIdx.x < off) red[threadIdx.x] += red[threadIdx.x + off];
        __syncthreads();
    }
    if (threadIdx.x == 0) g_cn[k] = 0.5f * red[0];
}
__global__ void k_init() {
    int m = blockIdx.x * blockDim.x + threadIdx.x;
    if (m < TOK) g_maxOrd[m] = 0u;
}
__global__ void k_prep_cb(const float* __restrict__ cb) {
    int i = blockIdx.x * 256 + threadIdx.x;
    float v = cb[i];
    __nv_bfloat16 h = __float2bfloat16(v);
    g_CBh[i] = h;
    g_CBl[i] = __float2bfloat16(v - __bfloat162float(h));
}
__global__ void k_prep_wout(const float* __restrict__ w) {
    int i = blockIdx.x * 256 + threadIdx.x;
    float v = w[i];
    __nv_bfloat16 h = __float2bfloat16(v);
    g_WOh[i] = h;
    g_WOl[i] = __float2bfloat16(v - __bfloat162float(h));
}

// ---------------------------------------------------------------------------
// GEMM1 (fp32 FFMA): bit-identical per-output accumulation chain to R1/R7/R8/R13.
#define G1_SMEM 32768
__global__ __launch_bounds__(256, 2) void k_gemm1(const float* __restrict__ x,
                                                  const float* __restrict__ w_in,
                                                  const float* __restrict__ b_in) {
    extern __shared__ char smem[];
    const uint32_t sb = smem_u32(smem);
    const int tid = threadIdx.x;
    const int ty = tid >> 4, tx = tid & 15;
    const int m0 = blockIdx.x * 128;
    const int n0 = blockIdx.y * 128;
    const int bb = m0 >> 11;
    const int tt0 = m0 & 2047;

    const int ac0 = tid,        akc0 = ac0 >> 6, apos0 = ac0 & 63;
    const int ac1 = tid + 256,  akc1 = ac1 >> 6, apos1 = ac1 & 63;
    const int brow = tid >> 1, bhalf = tid & 1;

    float acc[8][8];
#pragma unroll
    for (int i = 0; i < 8; i++)
#pragma unroll
        for (int j = 0; j < 8; j++) acc[i][j] = 0.f;

    float4 bp0, bp1;
    {
        const float* xbase = x + (size_t)((bb << 10)) * Tlen + (tt0 << 1);
        cpasync16(sb + (uint32_t)(akc0 * 1024 + apos0 * 16),
                  xbase + (size_t)akc0 * Tlen + apos0 * 4);
        cpasync16(sb + (uint32_t)(akc1 * 1024 + apos1 * 16),
                  xbase + (size_t)akc1 * Tlen + apos1 * 4);
        CP_COMMIT();
        const float* wp = w_in + (size_t)(n0 + brow) * 2048 + bhalf * 8;
        bp0 = *(const float4*)(wp);
        bp1 = *(const float4*)(wp + 4);
        const float* b4 = (const float*)&bp0;
        #pragma unroll
        for (int w = 0; w < 4; w++)
            *(float*)(smem + 8192 + (bhalf * 8 + w) * 512 + brow * 4) = b4[w];
        const float* b5 = (const float*)&bp1;
        #pragma unroll
        for (int w = 0; w < 4; w++)
            *(float*)(smem + 8192 + (bhalf * 8 + 4 + w) * 512 + brow * 4) = b5[w];
    }

#pragma unroll 1
    for (int c = 0; c < 128; c++) {
        const uint32_t bufo = (uint32_t)(c & 1) * 16384u;
        CP_WAIT0();
        __syncthreads();

        if (c < 127) {
            const int k1 = (c + 1) * 16;
            const uint32_t nb = (uint32_t)((c + 1) & 1) * 16384u;
            const float* xbase = x + (size_t)((bb << 10) + (k1 >> 1)) * Tlen + (tt0 << 1);
            cpasync16(sb + nb + (uint32_t)(akc0 * 1024 + apos0 * 16),
                      xbase + (size_t)akc0 * Tlen + apos0 * 4);
            cpasync16(sb + nb + (uint32_t)(akc1 * 1024 + apos1 * 16),
                      xbase + (size_t)akc1 * Tlen + apos1 * 4);
            CP_COMMIT();
            const float* wp = w_in + (size_t)(n0 + brow) * 2048 + k1 + bhalf * 8;
            bp0 = *(const float4*)(wp);
            bp1 = *(const float4*)(wp + 4);
        }

        const char* Ab = smem + bufo;
        const char* Bb = smem + bufo + 8192;
#pragma unroll
        for (int kc = 0; kc < 8; kc++) {
            float4 av[4];
#pragma unroll
            for (int q = 0; q < 4; q++)
                av[q] = *(const float4*)(Ab + kc * 1024 + ty * 64 + q * 16);
            const float* af = (const float*)av;
#pragma unroll
            for (int p = 0; p < 2; p++) {
                float4 bv0 = *(const float4*)(Bb + (2 * kc + p) * 512 + tx * 32);
                float4 bv1 = *(const float4*)(Bb + (2 * kc + p) * 512 + tx * 32 + 16);
                const float bf8[8] = {bv0.x, bv0.y, bv0.z, bv0.w,
                                      bv1.x, bv1.y, bv1.z, bv1.w};
#pragma unroll
                for (int i = 0; i < 8; i++)
#pragma unroll
                    for (int j = 0; j < 8; j++)
                        acc[i][j] = fmaf(af[2 * i + p], bf8[j], acc[i][j]);
            }
        }

        if (c < 127) {
            const uint32_t nb = (uint32_t)((c + 1) & 1) * 16384u;
            const float* b4 = (const float*)&bp0;
            #pragma unroll
            for (int w = 0; w < 4; w++)
                *(float*)(smem + nb + 8192 + (bhalf * 8 + w) * 512 + brow * 4) = b4[w];
            const float* b5 = (const float*)&bp1;
            #pragma unroll
            for (int w = 0; w < 4; w++)
                *(float*)(smem + nb + 8192 + (bhalf * 8 + 4 + w) * 512 + brow * 4) = b5[w];
        }
    }

    // epilogue: H (fp32 + bias), bf16 copy, partial |H|^2 per token row
    __syncthreads();
    float* sq = (float*)smem;              // [128 rows][17] padded
#pragma unroll
    for (int i = 0; i < 8; i++) {
        int m = m0 + ty * 8 + i;
        float* hp = g_H + (size_t)m * DVQ + n0 + tx * 8;
        float vv[8];
#pragma unroll
        for (int j = 0; j < 8; j++) vv[j] = acc[i][j] + b_in[n0 + tx * 8 + j];
        *(float4*)(hp)     = make_float4(vv[0], vv[1], vv[2], vv[3]);
        *(float4*)(hp + 4) = make_float4(vv[4], vv[5], vv[6], vv[7]);
        __nv_bfloat16 hb[8];
#pragma unroll
        for (int j = 0; j < 8; j++) hb[j] = __float2bfloat16(vv[j]);
        *(uint4*)(g_Hb + (size_t)m * DVQ + n0 + tx * 8) = *(uint4*)hb;
        float part = 0.f;
#pragma unroll
        for (int j = 0; j < 8; j++) part += vv[j] * vv[j];
        sq[(ty * 8 + i) * 17 + tx] = part;
    }
    __syncthreads();
    if (tid < 128) {
        float s = 0.f;
        #pragma unroll
        for (int t = 0; t < 16; t++) s += sq[tid * 17 + t];
        g_hnp[blockIdx.y * TOK + m0 + tid] = s;
    }
}

// ---------------------------------------------------------------------------
// GEMM2 (bf16 HMMA): approx scores S[m,k] = Hb·CBh - cn -> bf16 g_Sb[m][k] + row max
#define SC_STRIDE 132
#define G2_SMEM 69632
__global__ __launch_bounds__(256, 2) void k_gemm2() {
    extern __shared__ char smem[];
    const uint32_t sb = smem_u32(smem);
    const int tid = threadIdx.x, lane = tid & 31, wid = tid >> 5;
    const int wm = (wid & 1) * 64, wn = (wid >> 1) * 32;
    const int m0 = blockIdx.x * 128, n0 = blockIdx.y * 128;

    float acc[4][4][4];
#pragma unroll
    for (int i = 0; i < 4; i++)
#pragma unroll
        for (int j = 0; j < 4; j++)
#pragma unroll
            for (int q = 0; q < 4; q++) acc[i][j][q] = 0.f;

    const int lrow = tid >> 2, luc = tid & 3;
    const char* srcA = (const char*)(g_Hb  + (size_t)(m0 + lrow) * DVQ) + luc * 16;
    const char* srcA2 = (const char*)(g_Hb + (size_t)(m0 + 64 + lrow) * DVQ) + luc * 16;
    const char* srcB = (const char*)(g_CBh + (size_t)(n0 + lrow) * DVQ) + luc * 16;
    const char* srcB2 = (const char*)(g_CBh + (size_t)(n0 + 64 + lrow) * DVQ) + luc * 16;
    const uint32_t off1 = (uint32_t)(lrow * 128 + ((luc ^ (lrow & 7)) << 4));
    const uint32_t off2 = (uint32_t)((lrow + 64) * 128 + ((luc ^ (lrow & 7)) << 4));

    {
        cpasync16(sb + off1, srcA);
        cpasync16(sb + off2, srcA2);
        cpasync16(sb + 32768u + off1, srcB);
        cpasync16(sb + 32768u + off2, srcB2);
        CP_COMMIT();
    }
#pragma unroll 1
    for (int c = 0; c < 32; c++) {
        CP_WAIT0();
        __syncthreads();
        if (c < 31) {
            const uint32_t ao = (uint32_t)((c + 1) & 1) * 16384u;
            const uint32_t bo = 32768u + (uint32_t)((c + 1) & 1) * 16384u;
            const int kby = (c + 1) * 64;
            cpasync16(sb + ao + off1, srcA + kby);
            cpasync16(sb + ao + off2, srcA2 + kby);
            cpasync16(sb + bo + off1, srcB + kby);
            cpasync16(sb + bo + off2, srcB2 + kby);
            CP_COMMIT();
        }
        mma_chunk(sb + (uint32_t)(c & 1) * 16384u, sb + 32768u + (uint32_t)(c & 1) * 16384u,
                  wm, wn, lane, acc);
    }
    __syncthreads();

    float* sc = (float*)smem;
    const int g = lane >> 2, lam = lane & 3;
#pragma unroll
    for (int mi = 0; mi < 4; mi++)
#pragma unroll
        for (int ni = 0; ni < 4; ni++) {
            const int col = wn + 8 * ni + 2 * lam;
            const float cn0 = __ldg(g_cn + n0 + col), cn1 = __ldg(g_cn + n0 + col + 1);
#pragma unroll
            for (int h = 0; h < 2; h++) {
                const int row = wm + 16 * mi + g + 8 * h;
                sc[row * SC_STRIDE + col]     = acc[mi][ni][2 * h + 0] - cn0;
                sc[row * SC_STRIDE + col + 1] = acc[mi][ni][2 * h + 1] - cn1;
            }
        }
    __syncthreads();

    // coalesced [m][k] store
    {
        const int cp = (tid & 63) * 2;
        const int rg = tid >> 6;
        #pragma unroll 4
        for (int r = rg * 32; r < rg * 32 + 32; r++) {
            uint32_t v = pack2(__float2bfloat16(sc[r * SC_STRIDE + cp]),
                               __float2bfloat16(sc[r * SC_STRIDE + cp + 1]));
            *(uint32_t*)(g_Sb + (size_t)(m0 + r) * KCB + n0 + cp) = v;
        }
    }
    // per-row max
    {
        const int row = tid & 127, half = tid >> 7;
        float mx = -3.4e38f;
        #pragma unroll 4
        for (int j = 0; j < 64; j++) mx = fmaxf(mx, sc[row * SC_STRIDE + half * 64 + j]);
        float* pmax = (float*)(smem + 67584);
        pmax[row * 2 + half] = mx;
        __syncthreads();
        if (tid < 128) {
            float m2 = fmaxf(pmax[tid * 2], pmax[tid * 2 + 1]);
            unsigned u = __float_as_uint(m2);
            u = (m2 < 0.f) ? ~u : (u | 0x80000000u);
            atomicMax(&g_maxOrd[m0 + tid], u);
        }
    }
}

// ---------------------------------------------------------------------------
// Collect: one warp per token; vectorized coalesced reads of g_Sb[m][k]
#define DELTA 4.5f
__global__ __launch_bounds__(256) void k_collect() {
    const int lane = threadIdx.x & 31;
    const int m = blockIdx.x * 8 + (threadIdx.x >> 5);
    unsigned u = g_maxOrd[m];
    float mx = (u & 0x80000000u) ? __uint_as_float(u ^ 0x80000000u) : __uint_as_float(~u);
    const float thr = mx - DELTA;
    int cnt = 0;
    const __nv_bfloat16* row = g_Sb + (size_t)m * KCB;
#pragma unroll 1
    for (int j = 0; j < 8; j++) {
        const int k0 = j * 256 + lane * 8;
        uint4 v = *(const uint4*)(row + k0);
        const __nv_bfloat16* e = (const __nv_bfloat16*)&v;
#pragma unroll
        for (int q = 0; q < 8; q++) {
            bool pred = (__bfloat162float(e[q]) >= thr);
            unsigned bal = __ballot_sync(0xFFFFFFFFu, pred);
            if (pred) {
                int pos = cnt + __popc(bal & ((1u << lane) - 1));
                if (pos < 32) g_cand[m * 32 + pos] = k0 + q;
            }
            cnt += __popc(bal);
        }
    }
    if (lane == 0) g_candcnt[m] = cnt < 32 ? cnt : 32;
}

// Exact fp32 rescore: strict sequential ascending-d fmaf chain per candidate.
__global__ __launch_bounds__(128) void k_rescore(const float* __restrict__ cb,
                                                 float* __restrict__ idx_out) {
    const int wid = threadIdx.x >> 5, lid = threadIdx.x & 31;
    const int m = blockIdx.x * 4 + wid;
    const int cnt = g_candcnt[m];
    const float* hp = g_H + (size_t)m * DVQ;

    unsigned long long key = 0ULL;
    if (lid < cnt) {
        const int k = g_cand[m * 32 + lid];
        const float* cp = cb + (size_t)k * DVQ;
        float s = 0.f;
        #pragma unroll 8
        for (int d = 0; d < DVQ; d++) s = fmaf(hp[d], cp[d], s);
        const float scv = s - g_cn[k];
        unsigned uu = __float_as_uint(scv);
        uu = (scv < 0.f) ? ~uu : (uu | 0x80000000u);
        key = ((unsigned long long)uu << 32) |
              (unsigned long long)(0xFFFFFFFFu - (unsigned)k);
    }
#pragma unroll
    for (int o = 16; o > 0; o >>= 1) {
        unsigned long long other = __shfl_xor_sync(0xFFFFFFFFu, key, o);
        if (other > key) key = other;
    }
    if (lid == 0) {
        int bk = (int)(0xFFFFFFFFu - (unsigned)(key & 0xFFFFFFFFu));
        g_idx[m] = bk;
        idx_out[m] = (float)bk;
        unsigned uu = (unsigned)(key >> 32);
        g_sbest[m] = (uu & 0x80000000u) ? __uint_as_float(uu ^ 0x80000000u)
                                        : __uint_as_float(~uu);
    }
}

// ---------------------------------------------------------------------------
// Loss via identity: loss*N = sum_m |H_m|^2 - 2*sum_m s_best,m  (deterministic)
__global__ void k_loss_final(float* __restrict__ loss_out) {
    __shared__ float red[256];
    const int t = threadIdx.x;
    float acc = 0.f;
    for (int m = t; m < TOK; m += 256) {
        float hn = 0.f;
        #pragma unroll
        for (int b = 0; b < 8; b++) hn += g_hnp[b * TOK + m];
        acc += hn - 2.f * g_sbest[m];
    }
    red[t] = acc;
    __syncthreads();
    for (int off = 128; off > 0; off >>= 1) {
        if (t < off) red[t] += red[t + off];
        __syncthreads();
    }
    if (t == 0)
        loss_out[0] = red[0] / ((float)TOK * (float)DVQ);
}

// ---------------------------------------------------------------------------
// P-GEMM (bf16 HMMA, 3-product split): P[k][o] = Wout·cb_k + b_out.
#define GP_SMEM 69632
__global__ __launch_bounds__(256, 2) void k_pgemm(const float* __restrict__ b_out) {
    extern __shared__ char smem[];
    const uint32_t sb = smem_u32(smem);
    const int tid = threadIdx.x, lane = tid & 31, wid = tid >> 5;
    const int wm = (wid & 1) * 64, wn = (wid >> 1) * 32;
    const int m0 = blockIdx.x * 128, n0 = blockIdx.y * 128;   // m0: code rows

    float acc[4][4][4];
#pragma unroll
    for (int i = 0; i < 4; i++)
#pragma unroll
        for (int j = 0; j < 4; j++)
#pragma unroll
            for (int q = 0; q < 4; q++) acc[i][j][q] = 0.f;

    const int lrow = tid >> 2, luc = tid & 3;
    const uint32_t off1 = (uint32_t)(lrow * 128 + ((luc ^ (lrow & 7)) << 4));
    const uint32_t off2 = (uint32_t)((lrow + 64) * 128 + ((luc ^ (lrow & 7)) << 4));
    const size_t rowA1 = (size_t)(m0 + lrow) * DVQ;
    const size_t rowA2 = (size_t)(m0 + 64 + lrow) * DVQ;
    const size_t rowB1 = (size_t)(n0 + lrow) * DVQ;
    const size_t rowB2 = (size_t)(n0 + 64 + lrow) * DVQ;

    // seg: 0 -> (CBh,WOh), 1 -> (CBh,WOl), 2 -> (CBl,WOh); 32 chunks each
    {
        cpasync16(sb + off1, (const char*)(g_CBh + rowA1) + luc * 16);
        cpasync16(sb + off2, (const char*)(g_CBh + rowA2) + luc * 16);
        cpasync16(sb + 32768u + off1, (const char*)(g_WOh + rowB1) + luc * 16);
        cpasync16(sb + 32768u + off2, (const char*)(g_WOh + rowB2) + luc * 16);
        CP_COMMIT();
    }
#pragma unroll 1
    for (int c = 0; c < 96; c++) {
        CP_WAIT0();
        __syncthreads();
        if (c < 95) {
            const int c1 = c + 1;
            const int seg = c1 >> 5;
            const int kby = (c1 & 31) * 64 + luc * 16;
            const __nv_bfloat16* Ab = (seg == 2) ? g_CBl : g_CBh;
            const __nv_bfloat16* Bb = (seg == 1) ? g_WOl : g_WOh;
            const uint32_t ao = (uint32_t)(c1 & 1) * 16384u;
            const uint32_t bo = 32768u + (uint32_t)(c1 & 1) * 16384u;
            cpasync16(sb + ao + off1, (const char*)(Ab + rowA1) + kby);
            cpasync16(sb + ao + off2, (const char*)(Ab + rowA2) + kby);
            cpasync16(sb + bo + off1, (const char*)(Bb + rowB1) + kby);
            cpasync16(sb + bo + off2, (const char*)(Bb + rowB2) + kby);
            CP_COMMIT();
        }
        mma_chunk(sb + (uint32_t)(c & 1) * 16384u, sb + 32768u + (uint32_t)(c & 1) * 16384u,
                  wm, wn, lane, acc);
    }

    // epilogue: P[k][o] = acc + b_out[o], coalesced direct store
    const int g = lane >> 2, lam = lane & 3;
#pragma unroll
    for (int mi = 0; mi < 4; mi++)
#pragma unroll
        for (int ni = 0; ni < 4; ni++) {
            const int col = n0 + wn + 8 * ni + 2 * lam;
            const float b0 = __ldg(b_out + col), b1 = __ldg(b_out + col + 1);
#pragma unroll
            for (int h = 0; h < 2; h++) {
                const int k = m0 + wm + 16 * mi + g + 8 * h;
                *(float2*)(g_P + (size_t)k * CIN + col) =
                    make_float2(acc[mi][ni][2 * h + 0] + b0,
                                acc[mi][ni][2 * h + 1] + b1);
            }
        }
}

// ---------------------------------------------------------------------------
// Scatter (R15): lanes span m (-> contiguous t2 -> coalesced 256B stores);
// each warp owns 16 o-columns; P row gathers come from L2-resident g_P.
__global__ __launch_bounds__(256) void k_scatter(const float* __restrict__ xmask,
                                                 float* __restrict__ out) {
    __shared__ int sidx[128];
    const int tid = threadIdx.x;
    const int m0 = blockIdx.x * 128, n0 = blockIdx.y * 128;
    if (tid < 128) sidx[tid] = g_idx[m0 + tid];
    __syncthreads();

    const int w = tid >> 5, lane = tid & 31;
    const int b = m0 >> 11;
#pragma unroll
    for (int mg = 0; mg < 4; mg++) {
        const int rr = mg * 32 + lane;
        const size_t prow = (size_t)sidx[rr] * CIN;
        const int t2 = (m0 + rr) & 2047;
        const float2 mk = *(const float2*)(xmask + b * Tlen + 2 * t2);
        float* outb = out + 2 * t2;
#pragma unroll
        for (int oo = 0; oo < 16; oo++) {
            const int o = n0 + w * 16 + oo;
            const float v = __ldg(g_P + prow + o);
            *(float2*)(outb + (size_t)(b * CIN + o) * Tlen) =
                make_float2(v * mk.x, v * mk.y);
        }
    }
}

// ---------------------------------------------------------------------------
extern "C" void kernel_launch(void* const* d_in, const int* in_sizes, int n_in,
                              void* d_out, int out_size) {
    const float* x     = (const float*)d_in[0];
    const float* xmask = (const float*)d_in[1];
    const float* w_in  = (const float*)d_in[2];
    const float* b_in  = (const float*)d_in[3];
    const float* cb    = (const float*)d_in[4];
    const float* w_out = (const float*)d_in[5];
    const float* b_out = (const float*)d_in[6];
    float* out = (float*)d_out;

    const int loss_off = out_size - 1;
    const int idx_off  = out_size - 1 - TOK;

    cudaFuncSetAttribute(k_gemm1, cudaFuncAttributeMaxDynamicSharedMemorySize, G1_SMEM);
    cudaFuncSetAttribute(k_gemm2, cudaFuncAttributeMaxDynamicSharedMemorySize, G2_SMEM);
    cudaFuncSetAttribute(k_pgemm, cudaFuncAttributeMaxDynamicSharedMemorySize, GP_SMEM);

    k_cnorm<<<KCB, 256>>>(cb);
    k_init<<<TOK / 256, 256>>>();
    k_prep_cb<<<KCB * DVQ / 256, 256>>>(cb);
    k_prep_wout<<<CIN * DVQ / 256, 256>>>(w_out);
    k_pgemm<<<dim3(KCB / 128, CIN / 128), 256, GP_SMEM>>>(b_out);
    k_gemm1<<<dim3(TOK / 128, DVQ / 128), 256, G1_SMEM>>>(x, w_in, b_in);
    k_gemm2<<<dim3(TOK / 128, KCB / 128), 256, G2_SMEM>>>();
    k_collect<<<TOK / 8, 256>>>();
    k_rescore<<<TOK / 4, 128>>>(cb, out + idx_off);
    k_loss_final<<<1, 256>>>(out + loss_off);
    k_scatter<<<dim3(TOK / 128, CIN / 128), 256>>>(xmask, out);
}